// round 2
// baseline (speedup 1.0000x reference)
#include <cuda_runtime.h>
#include <math.h>

// ---------------- problem constants ----------------
namespace {
constexpr int Bn  = 128;
constexpr int Ln  = 128;
constexpr int DIN = 6;
constexpr int D   = 256;
constexpr int H   = 8;
constexpr int NL  = 6;
constexpr int NE  = 8;
constexpr int DFF = 1024;
constexpr int NOUT = 5;
constexpr int T   = Bn * Ln;     // 16384 tokens
constexpr int DK  = 32;
constexpr int MAXRB = 528;       // max grouped-GEMM row blocks (2T/64 + NE pad)
}

// ---------------- scratch (device globals; no allocation) ----------------
__device__ float d_h [T * D];
__device__ float d_qb[T * D];
__device__ float d_kb[T * D];
__device__ float d_vb[T * D];
__device__ float d_ao[T * D];
__device__ float d_hff[(size_t)2 * T * DFF];   // 134 MB
__device__ float d_eo [(size_t)2 * T * D];     // 33 MB
__device__ int   d_ti  [2 * T];
__device__ float d_tw  [2 * T];
__device__ int   d_posb[2 * T];
__device__ int   d_gtok[2 * T + 512];
__device__ int   d_counts [NE];
__device__ int   d_cursor [NE];
__device__ int   d_offsets[NE];
__device__ int   d_expEnd [NE];
__device__ int   d_blkExpert[MAXRB];
__device__ int   d_blkBase  [MAXRB];
__device__ int   d_numRB;

__device__ __forceinline__ float gelu_exact(float x) {
    return 0.5f * x * (1.0f + erff(x * 0.70710678118654752f));
}

// ---------------- embedding: h = x @ emb_w + emb_b ----------------
__global__ void embed_kernel(const float* __restrict__ x,
                             const float* __restrict__ ew,
                             const float* __restrict__ eb,
                             float* __restrict__ h) {
    int idx = blockIdx.x * blockDim.x + threadIdx.x;  // T*D threads
    int t = idx >> 8;
    int d = idx & 255;
    float s = eb[d];
#pragma unroll
    for (int k = 0; k < DIN; k++) s += x[t * DIN + k] * ew[k * D + d];
    h[idx] = s;
}

// ---------------- generic SGEMM: C[M,N] = A[M,K] @ W[K,N] (+bias/+resid/gelu) ----
// M multiple of 64 (grid.x = M/64), N multiple of 64 (grid.y = N/64), K mult of 16.
// flags: bit0 = +bias, bit1 = +resid, bit2 = gelu
__global__ void sgemm64(const float* __restrict__ A, const float* __restrict__ W,
                        const float* __restrict__ bias, const float* __restrict__ resid,
                        float* __restrict__ C, int K, int N, int flags) {
    __shared__ float As[16][64];
    __shared__ float Bs[16][64];
    const int bm = blockIdx.x, bn = blockIdx.y;
    const int tid = threadIdx.x;             // 256 threads
    const int tx = tid & 15, ty = tid >> 4;

    const int arow = tid >> 2;                // 0..63
    const int akv  = tid & 3;                 // which float4 of the 16-wide k tile
    const int brow = tid >> 4;                // 0..15 (k within tile)
    const int bnv  = tid & 15;                // 0..15 (float4 col)

    const float* Aptr = A + (size_t)(bm * 64 + arow) * K + akv * 4;
    const float* Wptr = W + (size_t)brow * N + bn * 64 + bnv * 4;

    float acc[4][4] = {};
    for (int k0 = 0; k0 < K; k0 += 16) {
        float4 a4 = *(const float4*)(Aptr + k0);
        As[akv * 4 + 0][arow] = a4.x;
        As[akv * 4 + 1][arow] = a4.y;
        As[akv * 4 + 2][arow] = a4.z;
        As[akv * 4 + 3][arow] = a4.w;
        *(float4*)&Bs[brow][bnv * 4] = *(const float4*)(Wptr + (size_t)k0 * N);
        __syncthreads();
#pragma unroll
        for (int kk = 0; kk < 16; kk++) {
            float4 av = *(const float4*)&As[kk][ty * 4];
            float4 bv = *(const float4*)&Bs[kk][tx * 4];
            float a[4] = {av.x, av.y, av.z, av.w};
            float b[4] = {bv.x, bv.y, bv.z, bv.w};
#pragma unroll
            for (int i = 0; i < 4; i++)
#pragma unroll
                for (int j = 0; j < 4; j++) acc[i][j] += a[i] * b[j];
        }
        __syncthreads();
    }
    const int row0 = bm * 64 + ty * 4;
    const int col0 = bn * 64 + tx * 4;
#pragma unroll
    for (int i = 0; i < 4; i++) {
#pragma unroll
        for (int j = 0; j < 4; j++) {
            float c = acc[i][j];
            if (flags & 1) c += bias[col0 + j];
            if (flags & 2) c += resid[(size_t)(row0 + i) * N + col0 + j];
            if (flags & 4) c = gelu_exact(c);
            C[(size_t)(row0 + i) * N + col0 + j] = c;
        }
    }
}

// ---------------- wave attention, one block per (b, head) ----------------
__global__ void attn_kernel(const float* __restrict__ Q, const float* __restrict__ K_,
                            const float* __restrict__ V,
                            const float* __restrict__ wf, const float* __restrict__ wp,
                            float* __restrict__ O) {
    const int b = blockIdx.x >> 3;
    const int hh = blockIdx.x & 7;
    __shared__ float ks[Ln][DK];
    __shared__ float vs[Ln][DK];
    __shared__ float wv[Ln];
    const int tid = threadIdx.x;   // 128
    const float freq = wf[hh], phase = wp[hh];
    const float scale = 0.17677669529663687f;  // DK^-0.5

    for (int idx = tid; idx < Ln * DK; idx += 128) {
        int l = idx >> 5, d = idx & 31;
        ks[l][d] = K_[(size_t)(b * Ln + l) * D + hh * DK + d];
        vs[l][d] = V[(size_t)(b * Ln + l) * D + hh * DK + d];
    }
    if (tid < Ln)
        wv[tid] = scale * cosf(6.283185307179586f * freq * (float)tid + phase);
    __syncthreads();

    float qr[DK];
#pragma unroll
    for (int d = 0; d < DK; d++) qr[d] = Q[(size_t)(b * Ln + tid) * D + hh * DK + d];

    // pass 1: row max
    float m = -1e30f;
    for (int kk = 0; kk < Ln; kk++) {
        float s = 0.f;
#pragma unroll
        for (int d = 0; d < DK; d++) s += qr[d] * ks[kk][d];
        s *= wv[kk];
        m = fmaxf(m, s);
    }
    // pass 2: exp + weighted accumulate
    float acc[DK] = {};
    float sum = 0.f;
    for (int kk = 0; kk < Ln; kk++) {
        float s = 0.f;
#pragma unroll
        for (int d = 0; d < DK; d++) s += qr[d] * ks[kk][d];
        s *= wv[kk];
        float p = __expf(s - m);
        sum += p;
#pragma unroll
        for (int d = 0; d < DK; d++) acc[d] += p * vs[kk][d];
    }
    const float inv = 1.0f / sum;
#pragma unroll
    for (int d = 0; d < DK; d++)
        O[(size_t)(b * Ln + tid) * D + hh * DK + d] = acc[d] * inv;
}

// ---------------- MoE router: top-2 over softmax(h @ rtw + rtb) ----------------
__global__ void moe_zero() {
    int i = threadIdx.x;
    if (i < NE) { d_counts[i] = 0; }
}

__global__ void router_kernel(const float* __restrict__ h,
                              const float* __restrict__ rtw,
                              const float* __restrict__ rtb) {
    const int gw = (blockIdx.x * blockDim.x + threadIdx.x) >> 5;
    const int lane = threadIdx.x & 31;
    const int nwarp = (gridDim.x * blockDim.x) >> 5;
    for (int t = gw; t < T; t += nwarp) {
        float lg[NE] = {};
        for (int d = lane; d < D; d += 32) {
            float hv = h[(size_t)t * D + d];
#pragma unroll
            for (int e = 0; e < NE; e++) lg[e] += hv * rtw[d * NE + e];
        }
#pragma unroll
        for (int e = 0; e < NE; e++)
#pragma unroll
            for (int off = 16; off; off >>= 1)
                lg[e] += __shfl_xor_sync(0xffffffffu, lg[e], off);
        if (lane == 0) {
#pragma unroll
            for (int e = 0; e < NE; e++) lg[e] += rtb[e];
            int e0 = 0;
#pragma unroll
            for (int e = 1; e < NE; e++) if (lg[e] > lg[e0]) e0 = e;
            int e1 = (e0 == 0) ? 1 : 0;
#pragma unroll
            for (int e = 0; e < NE; e++)
                if (e != e0 && lg[e] > lg[e1]) e1 = e;
            float w0 = 1.0f / (1.0f + __expf(lg[e1] - lg[e0]));  // renormalized top-2
            d_ti[t * 2]     = e0;
            d_ti[t * 2 + 1] = e1;
            d_tw[t * 2]     = w0;
            d_tw[t * 2 + 1] = 1.0f - w0;
            atomicAdd(&d_counts[e0], 1);
            atomicAdd(&d_counts[e1], 1);
        }
    }
}

__global__ void moe_scan() {
    if (threadIdx.x == 0) {
        int off = 0, rb = 0;
        for (int e = 0; e < NE; e++) {
            d_offsets[e] = off;
            int c = d_counts[e];
            d_expEnd[e] = off + c;
            int nb = (c + 63) >> 6;
            for (int j = 0; j < nb; j++) {
                d_blkExpert[rb] = e;
                d_blkBase[rb]   = off + (j << 6);
                rb++;
            }
            off += c;
            d_cursor[e] = 0;
        }
        d_numRB = rb;
    }
}

__global__ void scatter_kernel() {
    int idx = blockIdx.x * blockDim.x + threadIdx.x;
    if (idx >= 2 * T) return;
    int e = d_ti[idx];
    int p = atomicAdd(&d_cursor[e], 1);
    int r = d_offsets[e] + p;
    d_gtok[r]  = idx >> 1;
    d_posb[idx] = r;
}

// ---------------- grouped expert GEMM (per-row-block expert mapping) -------
// C[r, :] for gathered row r; W/bias selected by block's expert.
// useGather: A row = h[gtok[r]]; else A row = Abase[r].
__global__ void moe_gemm(const float* __restrict__ Abase, int useGather,
                         const float* __restrict__ Wbase,
                         const float* __restrict__ biasBase,
                         float* __restrict__ Cbase,
                         int K, int N, int actGelu) {
    const int rb = blockIdx.x;
    if (rb >= d_numRB) return;
    const int e    = d_blkExpert[rb];
    const int base = d_blkBase[rb];
    const int rend = d_expEnd[e];
    const float* W    = Wbase + (size_t)e * K * N;
    const float* bias = biasBase + (size_t)e * N;

    __shared__ float As[16][64];
    __shared__ float Bs[16][64];
    const int bn = blockIdx.y;
    const int tid = threadIdx.x;
    const int tx = tid & 15, ty = tid >> 4;

    const int arow = tid >> 2;
    const int akv  = tid & 3;
    const int brow = tid >> 4;
    const int bnv  = tid & 15;

    int r = base + arow;
    bool avalid = r < rend;
    size_t asrc;
    if (useGather) asrc = (size_t)d_gtok[avalid ? r : base];
    else           asrc = (size_t)(avalid ? r : base);
    const float* Aptr = Abase + asrc * K + akv * 4;
    const float* Wptr = W + (size_t)brow * N + bn * 64 + bnv * 4;

    float acc[4][4] = {};
    for (int k0 = 0; k0 < K; k0 += 16) {
        float4 a4 = *(const float4*)(Aptr + k0);
        As[akv * 4 + 0][arow] = a4.x;
        As[akv * 4 + 1][arow] = a4.y;
        As[akv * 4 + 2][arow] = a4.z;
        As[akv * 4 + 3][arow] = a4.w;
        *(float4*)&Bs[brow][bnv * 4] = *(const float4*)(Wptr + (size_t)k0 * N);
        __syncthreads();
#pragma unroll
        for (int kk = 0; kk < 16; kk++) {
            float4 av = *(const float4*)&As[kk][ty * 4];
            float4 bv = *(const float4*)&Bs[kk][tx * 4];
            float a[4] = {av.x, av.y, av.z, av.w};
            float b[4] = {bv.x, bv.y, bv.z, bv.w};
#pragma unroll
            for (int i = 0; i < 4; i++)
#pragma unroll
                for (int j = 0; j < 4; j++) acc[i][j] += a[i] * b[j];
        }
        __syncthreads();
    }
    const int col0 = bn * 64 + tx * 4;
#pragma unroll
    for (int i = 0; i < 4; i++) {
        int rr = base + ty * 4 + i;
        if (rr >= rend) continue;
#pragma unroll
        for (int j = 0; j < 4; j++) {
            float c = acc[i][j] + bias[col0 + j];
            if (actGelu) c = gelu_exact(c);
            Cbase[(size_t)rr * N + col0 + j] = c;
        }
    }
}

// ---------------- combine: h += w0*eo[pos0] + w1*eo[pos1] ----------------
__global__ void combine_kernel(float* __restrict__ h) {
    int idx = blockIdx.x * blockDim.x + threadIdx.x;  // T*D
    int t = idx >> 8;
    int d = idx & 255;
    float a = d_tw[t * 2]     * d_eo[(size_t)d_posb[t * 2]     * D + d];
    float b = d_tw[t * 2 + 1] * d_eo[(size_t)d_posb[t * 2 + 1] * D + d];
    h[idx] += a + b;
}

// ---------------- final LN (last position only) + heads ----------------
__global__ void final_kernel(const float* __restrict__ h,
                             const float* __restrict__ g, const float* __restrict__ be,
                             const float* __restrict__ pw, const float* __restrict__ pb,
                             const float* __restrict__ uw, const float* __restrict__ ub,
                             float* __restrict__ out) {
    const int b = blockIdx.x;
    const int d = threadIdx.x;  // 256
    const int t = b * Ln + (Ln - 1);
    __shared__ float row[D];
    __shared__ float sred[8];
    __shared__ float mu_s, rs_s;

    float v = h[(size_t)t * D + d];
    float s = v;
#pragma unroll
    for (int o = 16; o; o >>= 1) s += __shfl_xor_sync(0xffffffffu, s, o);
    if ((d & 31) == 0) sred[d >> 5] = s;
    __syncthreads();
    if (d == 0) {
        float m = 0;
#pragma unroll
        for (int i = 0; i < 8; i++) m += sred[i];
        mu_s = m / (float)D;
    }
    __syncthreads();
    const float mu = mu_s;
    const float dv = v - mu;
    float s2 = dv * dv;
#pragma unroll
    for (int o = 16; o; o >>= 1) s2 += __shfl_xor_sync(0xffffffffu, s2, o);
    if ((d & 31) == 0) sred[d >> 5] = s2;
    __syncthreads();
    if (d == 0) {
        float m = 0;
#pragma unroll
        for (int i = 0; i < 8; i++) m += sred[i];
        rs_s = rsqrtf(m / (float)D + 1e-5f);
    }
    __syncthreads();
    row[d] = dv * rs_s * g[d] + be[d];
    __syncthreads();

    if (d < 2 * NOUT) {
        int which = d / NOUT, j = d % NOUT;
        const float* Wm = which ? uw : pw;
        float acc = which ? ub[j] : pb[j];
        for (int dd = 0; dd < D; dd++) acc += row[dd] * Wm[dd * NOUT + j];
        if (which) acc = (acc > 20.0f) ? acc : log1pf(__expf(acc));  // softplus
        out[which * Bn * NOUT + b * NOUT + j] = acc;
    }
}

// ---------------- launch ----------------
extern "C" void kernel_launch(void* const* d_in, const int* in_sizes, int n_in,
                              void* d_out, int out_size) {
    const float* x      = (const float*)d_in[0];
    const float* emb_w  = (const float*)d_in[1];
    const float* emb_b  = (const float*)d_in[2];
    const float* wq     = (const float*)d_in[3];
    const float* wk     = (const float*)d_in[4];
    const float* wv     = (const float*)d_in[5];
    const float* wo     = (const float*)d_in[6];
    const float* wfreq  = (const float*)d_in[7];
    const float* wphase = (const float*)d_in[8];
    const float* rtw    = (const float*)d_in[9];
    const float* rtb    = (const float*)d_in[10];
    const float* ew1    = (const float*)d_in[11];
    const float* eb1    = (const float*)d_in[12];
    const float* ew2    = (const float*)d_in[13];
    const float* eb2    = (const float*)d_in[14];
    const float* ln_g   = (const float*)d_in[15];
    const float* ln_b   = (const float*)d_in[16];
    const float* pred_w = (const float*)d_in[17];
    const float* pred_b = (const float*)d_in[18];
    const float* unc_w  = (const float*)d_in[19];
    const float* unc_b  = (const float*)d_in[20];
    float* out = (float*)d_out;

    float *h, *q, *k, *v, *ao, *hff, *eo;
    cudaGetSymbolAddress((void**)&h,   d_h);
    cudaGetSymbolAddress((void**)&q,   d_qb);
    cudaGetSymbolAddress((void**)&k,   d_kb);
    cudaGetSymbolAddress((void**)&v,   d_vb);
    cudaGetSymbolAddress((void**)&ao,  d_ao);
    cudaGetSymbolAddress((void**)&hff, d_hff);
    cudaGetSymbolAddress((void**)&eo,  d_eo);

    embed_kernel<<<(T * D) / 256, 256>>>(x, emb_w, emb_b, h);

    dim3 gD(T / 64, D / 64);   // (256, 4)
    for (int i = 0; i < NL; i++) {
        sgemm64<<<gD, 256>>>(h, wq + (size_t)i * D * D, nullptr, nullptr, q, D, D, 0);
        sgemm64<<<gD, 256>>>(h, wk + (size_t)i * D * D, nullptr, nullptr, k, D, D, 0);
        sgemm64<<<gD, 256>>>(h, wv + (size_t)i * D * D, nullptr, nullptr, v, D, D, 0);
        attn_kernel<<<Bn * H, 128>>>(q, k, v, wfreq + i * H, wphase + i * H, ao);
        // h = ao @ Wo + h  (residual)
        sgemm64<<<gD, 256>>>(ao, wo + (size_t)i * D * D, nullptr, h, h, D, D, 2);

        if (i % 2 == 0) {
            int m = i / 2;
            moe_zero<<<1, 32>>>();
            router_kernel<<<128, 128>>>(h, rtw + (size_t)m * D * NE, rtb + m * NE);
            moe_scan<<<1, 1>>>();
            scatter_kernel<<<(2 * T) / 256, 256>>>();
            // hff = gelu(h[gtok] @ w1_e + b1_e)
            moe_gemm<<<dim3(MAXRB, DFF / 64), 256>>>(
                h, 1, ew1 + (size_t)m * NE * D * DFF, eb1 + (size_t)m * NE * DFF,
                hff, D, DFF, 1);
            // eo = hff @ w2_e + b2_e
            moe_gemm<<<dim3(MAXRB, D / 64), 256>>>(
                hff, 0, ew2 + (size_t)m * NE * DFF * D, eb2 + (size_t)m * NE * D,
                eo, DFF, D, 0);
            combine_kernel<<<(T * D) / 256, 256>>>(h);
        }
    }

    final_kernel<<<Bn, 256>>>(h, ln_g, ln_b, pred_w, pred_b, unc_w, unc_b, out);
}

// round 4
// speedup vs baseline: 1.1746x; 1.1746x over previous
#include <cuda_runtime.h>
#include <math.h>

// ---------------- problem constants ----------------
namespace {
constexpr int Bn  = 128;
constexpr int Ln  = 128;
constexpr int DIN = 6;
constexpr int D   = 256;
constexpr int H   = 8;
constexpr int NL  = 6;
constexpr int NE  = 8;
constexpr int DFF = 1024;
constexpr int NOUT = 5;
constexpr int T   = Bn * Ln;     // 16384 tokens
constexpr int DK  = 32;
constexpr int MAXRB = 272;       // grouped-GEMM 128-row blocks: 2T/128 + NE pad
}

// ---------------- scratch (device globals; no allocation) ----------------
__device__ float d_h [T * D];
__device__ float d_qb[T * D];
__device__ float d_kb[T * D];
__device__ float d_vb[T * D];
__device__ float d_ao[T * D];
__device__ float d_hff[(size_t)2 * T * DFF];   // 134 MB
__device__ float d_eo [(size_t)2 * T * D];     // 33 MB
__device__ int   d_ti  [2 * T];
__device__ float d_tw  [2 * T];
__device__ int   d_posb[2 * T];
__device__ int   d_gtok[2 * T + 512];
__device__ int   d_counts [NE];
__device__ int   d_cursor [NE];
__device__ int   d_offsets[NE];
__device__ int   d_expEnd [NE];
__device__ int   d_blkExpert[MAXRB];
__device__ int   d_blkBase  [MAXRB];
__device__ int   d_numRB;

__device__ __forceinline__ float gelu_exact(float x) {
    return 0.5f * x * (1.0f + erff(x * 0.70710678118654752f));
}

// ---------------- embedding: h = x @ emb_w + emb_b ----------------
__global__ void embed_kernel(const float* __restrict__ x,
                             const float* __restrict__ ew,
                             const float* __restrict__ eb,
                             float* __restrict__ h) {
    int idx = blockIdx.x * blockDim.x + threadIdx.x;  // T*D threads
    int t = idx >> 8;
    int d = idx & 255;
    float s = eb[d];
#pragma unroll
    for (int k = 0; k < DIN; k++) s += x[t * DIN + k] * ew[k * D + d];
    h[idx] = s;
}

// ============ 128x128x16 fp32 GEMM, 256 threads, 8x8 micro-tile ============
// C[M,N] = A[M,K] @ W[K,N] (+bias/+resid/gelu).  M%128==0, N%128==0, K%16==0.
// flags: bit0=+bias, bit1=+resid, bit2=gelu
__global__ void __launch_bounds__(256, 2)
sgemm128(const float* __restrict__ A, const float* __restrict__ W,
         const float* __restrict__ bias, const float* __restrict__ resid,
         float* __restrict__ C, int K, int N, int flags) {
    __shared__ float As[2][16][128];
    __shared__ float Bs[2][16][128];
    const int bm = blockIdx.x, bn = blockIdx.y;
    const int tid = threadIdx.x;
    const int tx = tid & 15, ty = tid >> 4;

    // A-load mapping: 2 float4 per thread, transposed store
    const int arow = tid >> 1;             // 0..127
    const int akb  = (tid & 1) * 2;        // k-chunk base {0,2}
    // B-load mapping: 2 float4 per thread
    const int brow = tid >> 5;             // 0..7 (+8 on 2nd)
    const int bcol = (tid & 31) * 4;       // 0..124

    const float* Aptr = A + (size_t)(bm * 128 + arow) * K;
    const float* Wptr = W + (size_t)bn * 128 + bcol;

    float acc[8][8] = {};

    // initial tile -> buf 0
    {
        float4 a0 = *(const float4*)(Aptr + akb * 4);
        float4 a1 = *(const float4*)(Aptr + akb * 4 + 4);
        As[0][akb * 4 + 0][arow] = a0.x; As[0][akb * 4 + 1][arow] = a0.y;
        As[0][akb * 4 + 2][arow] = a0.z; As[0][akb * 4 + 3][arow] = a0.w;
        As[0][akb * 4 + 4][arow] = a1.x; As[0][akb * 4 + 5][arow] = a1.y;
        As[0][akb * 4 + 6][arow] = a1.z; As[0][akb * 4 + 7][arow] = a1.w;
        *(float4*)&Bs[0][brow][bcol]     = *(const float4*)(Wptr + (size_t)brow * N);
        *(float4*)&Bs[0][brow + 8][bcol] = *(const float4*)(Wptr + (size_t)(brow + 8) * N);
    }
    __syncthreads();

    int buf = 0;
    for (int k0 = 0; k0 < K; k0 += 16) {
        const bool more = (k0 + 16) < K;
        float4 pa0, pa1, pb0, pb1;
        if (more) {
            pa0 = *(const float4*)(Aptr + k0 + 16 + akb * 4);
            pa1 = *(const float4*)(Aptr + k0 + 16 + akb * 4 + 4);
            pb0 = *(const float4*)(Wptr + (size_t)(k0 + 16 + brow) * N);
            pb1 = *(const float4*)(Wptr + (size_t)(k0 + 16 + brow + 8) * N);
        }
#pragma unroll
        for (int kk = 0; kk < 16; kk++) {
            float4 av0 = *(const float4*)&As[buf][kk][ty * 8];
            float4 av1 = *(const float4*)&As[buf][kk][ty * 8 + 4];
            float4 bv0 = *(const float4*)&Bs[buf][kk][tx * 8];
            float4 bv1 = *(const float4*)&Bs[buf][kk][tx * 8 + 4];
            float a[8] = {av0.x, av0.y, av0.z, av0.w, av1.x, av1.y, av1.z, av1.w};
            float b[8] = {bv0.x, bv0.y, bv0.z, bv0.w, bv1.x, bv1.y, bv1.z, bv1.w};
#pragma unroll
            for (int i = 0; i < 8; i++)
#pragma unroll
                for (int j = 0; j < 8; j++) acc[i][j] += a[i] * b[j];
        }
        if (more) {
            int nb = buf ^ 1;
            As[nb][akb * 4 + 0][arow] = pa0.x; As[nb][akb * 4 + 1][arow] = pa0.y;
            As[nb][akb * 4 + 2][arow] = pa0.z; As[nb][akb * 4 + 3][arow] = pa0.w;
            As[nb][akb * 4 + 4][arow] = pa1.x; As[nb][akb * 4 + 5][arow] = pa1.y;
            As[nb][akb * 4 + 6][arow] = pa1.z; As[nb][akb * 4 + 7][arow] = pa1.w;
            *(float4*)&Bs[nb][brow][bcol]     = pb0;
            *(float4*)&Bs[nb][brow + 8][bcol] = pb1;
            __syncthreads();
            buf = nb;
        }
    }

    const int row0 = bm * 128 + ty * 8;
    const int col0 = bn * 128 + tx * 8;
#pragma unroll
    for (int i = 0; i < 8; i++) {
        float4 o0 = make_float4(acc[i][0], acc[i][1], acc[i][2], acc[i][3]);
        float4 o1 = make_float4(acc[i][4], acc[i][5], acc[i][6], acc[i][7]);
        if (flags & 1) {
            o0.x += bias[col0 + 0]; o0.y += bias[col0 + 1];
            o0.z += bias[col0 + 2]; o0.w += bias[col0 + 3];
            o1.x += bias[col0 + 4]; o1.y += bias[col0 + 5];
            o1.z += bias[col0 + 6]; o1.w += bias[col0 + 7];
        }
        if (flags & 2) {
            float4 r0 = *(const float4*)&resid[(size_t)(row0 + i) * N + col0];
            float4 r1 = *(const float4*)&resid[(size_t)(row0 + i) * N + col0 + 4];
            o0.x += r0.x; o0.y += r0.y; o0.z += r0.z; o0.w += r0.w;
            o1.x += r1.x; o1.y += r1.y; o1.z += r1.z; o1.w += r1.w;
        }
        if (flags & 4) {
            o0.x = gelu_exact(o0.x); o0.y = gelu_exact(o0.y);
            o0.z = gelu_exact(o0.z); o0.w = gelu_exact(o0.w);
            o1.x = gelu_exact(o1.x); o1.y = gelu_exact(o1.y);
            o1.z = gelu_exact(o1.z); o1.w = gelu_exact(o1.w);
        }
        *(float4*)&C[(size_t)(row0 + i) * N + col0]     = o0;
        *(float4*)&C[(size_t)(row0 + i) * N + col0 + 4] = o1;
    }
}

// ---------------- wave attention, one block per (b, head) ----------------
__global__ void attn_kernel(const float* __restrict__ Q, const float* __restrict__ K_,
                            const float* __restrict__ V,
                            const float* __restrict__ wf, const float* __restrict__ wp,
                            float* __restrict__ O) {
    const int b = blockIdx.x >> 3;
    const int hh = blockIdx.x & 7;
    __shared__ float ks[Ln][DK];
    __shared__ float vs[Ln][DK];
    __shared__ float wv[Ln];
    const int tid = threadIdx.x;   // 128
    const float freq = wf[hh], phase = wp[hh];
    const float scale = 0.17677669529663687f;  // DK^-0.5

    for (int idx = tid; idx < Ln * DK; idx += 128) {
        int l = idx >> 5, d = idx & 31;
        ks[l][d] = K_[(size_t)(b * Ln + l) * D + hh * DK + d];
        vs[l][d] = V[(size_t)(b * Ln + l) * D + hh * DK + d];
    }
    if (tid < Ln)
        wv[tid] = scale * cosf(6.283185307179586f * freq * (float)tid + phase);
    __syncthreads();

    float qr[DK];
#pragma unroll
    for (int d = 0; d < DK; d++) qr[d] = Q[(size_t)(b * Ln + tid) * D + hh * DK + d];

    float m = -1e30f;
    for (int kk = 0; kk < Ln; kk++) {
        float s = 0.f;
#pragma unroll
        for (int d = 0; d < DK; d++) s += qr[d] * ks[kk][d];
        s *= wv[kk];
        m = fmaxf(m, s);
    }
    float acc[DK] = {};
    float sum = 0.f;
    for (int kk = 0; kk < Ln; kk++) {
        float s = 0.f;
#pragma unroll
        for (int d = 0; d < DK; d++) s += qr[d] * ks[kk][d];
        s *= wv[kk];
        float p = __expf(s - m);
        sum += p;
#pragma unroll
        for (int d = 0; d < DK; d++) acc[d] += p * vs[kk][d];
    }
    const float inv = 1.0f / sum;
#pragma unroll
    for (int d = 0; d < DK; d++)
        O[(size_t)(b * Ln + tid) * D + hh * DK + d] = acc[d] * inv;
}

// ---------------- MoE router ----------------
__global__ void moe_zero() {
    int i = threadIdx.x;
    if (i < NE) { d_counts[i] = 0; }
}

__global__ void router_kernel(const float* __restrict__ h,
                              const float* __restrict__ rtw,
                              const float* __restrict__ rtb) {
    const int gw = (blockIdx.x * blockDim.x + threadIdx.x) >> 5;
    const int lane = threadIdx.x & 31;
    const int nwarp = (gridDim.x * blockDim.x) >> 5;
    for (int t = gw; t < T; t += nwarp) {
        float lg[NE] = {};
        for (int d = lane; d < D; d += 32) {
            float hv = h[(size_t)t * D + d];
#pragma unroll
            for (int e = 0; e < NE; e++) lg[e] += hv * rtw[d * NE + e];
        }
#pragma unroll
        for (int e = 0; e < NE; e++)
#pragma unroll
            for (int off = 16; off; off >>= 1)
                lg[e] += __shfl_xor_sync(0xffffffffu, lg[e], off);
        if (lane == 0) {
#pragma unroll
            for (int e = 0; e < NE; e++) lg[e] += rtb[e];
            int e0 = 0;
#pragma unroll
            for (int e = 1; e < NE; e++) if (lg[e] > lg[e0]) e0 = e;
            int e1 = (e0 == 0) ? 1 : 0;
#pragma unroll
            for (int e = 0; e < NE; e++)
                if (e != e0 && lg[e] > lg[e1]) e1 = e;
            float w0 = 1.0f / (1.0f + __expf(lg[e1] - lg[e0]));
            d_ti[t * 2]     = e0;
            d_ti[t * 2 + 1] = e1;
            d_tw[t * 2]     = w0;
            d_tw[t * 2 + 1] = 1.0f - w0;
            atomicAdd(&d_counts[e0], 1);
            atomicAdd(&d_counts[e1], 1);
        }
    }
}

__global__ void moe_scan() {
    if (threadIdx.x == 0) {
        int off = 0, rb = 0;
        for (int e = 0; e < NE; e++) {
            d_offsets[e] = off;
            int c = d_counts[e];
            d_expEnd[e] = off + c;
            int nb = (c + 127) >> 7;
            for (int j = 0; j < nb; j++) {
                d_blkExpert[rb] = e;
                d_blkBase[rb]   = off + (j << 7);
                rb++;
            }
            off += c;
            d_cursor[e] = 0;
        }
        d_numRB = rb;
    }
}

__global__ void scatter_kernel() {
    int idx = blockIdx.x * blockDim.x + threadIdx.x;
    if (idx >= 2 * T) return;
    int e = d_ti[idx];
    int p = atomicAdd(&d_cursor[e], 1);
    int r = d_offsets[e] + p;
    d_gtok[r]  = idx >> 1;
    d_posb[idx] = r;
}

// ============ grouped expert GEMM, 128x128x16, 8x8 micro-tile ============
__global__ void __launch_bounds__(256, 2)
moe_gemm128(const float* __restrict__ Abase, int useGather,
            const float* __restrict__ Wbase,
            const float* __restrict__ biasBase,
            float* __restrict__ Cbase,
            int K, int N, int actGelu) {
    const int rb = blockIdx.x;
    if (rb >= d_numRB) return;
    const int e    = d_blkExpert[rb];
    const int base = d_blkBase[rb];
    const int rend = d_expEnd[e];
    const float* W    = Wbase + (size_t)e * K * N;
    const float* bias = biasBase + (size_t)e * N;

    __shared__ float As[2][16][128];
    __shared__ float Bs[2][16][128];
    const int bn = blockIdx.y;
    const int tid = threadIdx.x;
    const int tx = tid & 15, ty = tid >> 4;

    const int arow = tid >> 1;
    const int akb  = (tid & 1) * 2;
    const int brow = tid >> 5;
    const int bcol = (tid & 31) * 4;

    int r = base + arow;
    bool avalid = r < rend;
    size_t asrc;
    if (useGather) asrc = (size_t)d_gtok[avalid ? r : base];
    else           asrc = (size_t)(avalid ? r : base);
    const float* Aptr = Abase + asrc * K;
    const float* Wptr = W + (size_t)bn * 128 + bcol;

    float acc[8][8] = {};

    {
        float4 a0 = *(const float4*)(Aptr + akb * 4);
        float4 a1 = *(const float4*)(Aptr + akb * 4 + 4);
        As[0][akb * 4 + 0][arow] = a0.x; As[0][akb * 4 + 1][arow] = a0.y;
        As[0][akb * 4 + 2][arow] = a0.z; As[0][akb * 4 + 3][arow] = a0.w;
        As[0][akb * 4 + 4][arow] = a1.x; As[0][akb * 4 + 5][arow] = a1.y;
        As[0][akb * 4 + 6][arow] = a1.z; As[0][akb * 4 + 7][arow] = a1.w;
        *(float4*)&Bs[0][brow][bcol]     = *(const float4*)(Wptr + (size_t)brow * N);
        *(float4*)&Bs[0][brow + 8][bcol] = *(const float4*)(Wptr + (size_t)(brow + 8) * N);
    }
    __syncthreads();

    int buf = 0;
    for (int k0 = 0; k0 < K; k0 += 16) {
        const bool more = (k0 + 16) < K;
        float4 pa0, pa1, pb0, pb1;
        if (more) {
            pa0 = *(const float4*)(Aptr + k0 + 16 + akb * 4);
            pa1 = *(const float4*)(Aptr + k0 + 16 + akb * 4 + 4);
            pb0 = *(const float4*)(Wptr + (size_t)(k0 + 16 + brow) * N);
            pb1 = *(const float4*)(Wptr + (size_t)(k0 + 16 + brow + 8) * N);
        }
#pragma unroll
        for (int kk = 0; kk < 16; kk++) {
            float4 av0 = *(const float4*)&As[buf][kk][ty * 8];
            float4 av1 = *(const float4*)&As[buf][kk][ty * 8 + 4];
            float4 bv0 = *(const float4*)&Bs[buf][kk][tx * 8];
            float4 bv1 = *(const float4*)&Bs[buf][kk][tx * 8 + 4];
            float a[8] = {av0.x, av0.y, av0.z, av0.w, av1.x, av1.y, av1.z, av1.w};
            float b[8] = {bv0.x, bv0.y, bv0.z, bv0.w, bv1.x, bv1.y, bv1.z, bv1.w};
#pragma unroll
            for (int i = 0; i < 8; i++)
#pragma unroll
                for (int j = 0; j < 8; j++) acc[i][j] += a[i] * b[j];
        }
        if (more) {
            int nb = buf ^ 1;
            As[nb][akb * 4 + 0][arow] = pa0.x; As[nb][akb * 4 + 1][arow] = pa0.y;
            As[nb][akb * 4 + 2][arow] = pa0.z; As[nb][akb * 4 + 3][arow] = pa0.w;
            As[nb][akb * 4 + 4][arow] = pa1.x; As[nb][akb * 4 + 5][arow] = pa1.y;
            As[nb][akb * 4 + 6][arow] = pa1.z; As[nb][akb * 4 + 7][arow] = pa1.w;
            *(float4*)&Bs[nb][brow][bcol]     = pb0;
            *(float4*)&Bs[nb][brow + 8][bcol] = pb1;
            __syncthreads();
            buf = nb;
        }
    }

    const int col0 = bn * 128 + tx * 8;
#pragma unroll
    for (int i = 0; i < 8; i++) {
        int rr = base + ty * 8 + i;
        if (rr >= rend) continue;
        float4 o0 = make_float4(acc[i][0] + bias[col0 + 0], acc[i][1] + bias[col0 + 1],
                                acc[i][2] + bias[col0 + 2], acc[i][3] + bias[col0 + 3]);
        float4 o1 = make_float4(acc[i][4] + bias[col0 + 4], acc[i][5] + bias[col0 + 5],
                                acc[i][6] + bias[col0 + 6], acc[i][7] + bias[col0 + 7]);
        if (actGelu) {
            o0.x = gelu_exact(o0.x); o0.y = gelu_exact(o0.y);
            o0.z = gelu_exact(o0.z); o0.w = gelu_exact(o0.w);
            o1.x = gelu_exact(o1.x); o1.y = gelu_exact(o1.y);
            o1.z = gelu_exact(o1.z); o1.w = gelu_exact(o1.w);
        }
        *(float4*)&Cbase[(size_t)rr * N + col0]     = o0;
        *(float4*)&Cbase[(size_t)rr * N + col0 + 4] = o1;
    }
}

// ---------------- combine: h += w0*eo[pos0] + w1*eo[pos1] ----------------
__global__ void combine_kernel(float* __restrict__ h) {
    int idx = blockIdx.x * blockDim.x + threadIdx.x;  // T*D
    int t = idx >> 8;
    int d = idx & 255;
    float a = d_tw[t * 2]     * d_eo[(size_t)d_posb[t * 2]     * D + d];
    float b = d_tw[t * 2 + 1] * d_eo[(size_t)d_posb[t * 2 + 1] * D + d];
    h[idx] += a + b;
}

// ---------------- final LN (last position only) + heads ----------------
__global__ void final_kernel(const float* __restrict__ h,
                             const float* __restrict__ g, const float* __restrict__ be,
                             const float* __restrict__ pw, const float* __restrict__ pb,
                             const float* __restrict__ uw, const float* __restrict__ ub,
                             float* __restrict__ out) {
    const int b = blockIdx.x;
    const int d = threadIdx.x;  // 256
    const int t = b * Ln + (Ln - 1);
    __shared__ float row[D];
    __shared__ float sred[8];
    __shared__ float mu_s, rs_s;

    float v = h[(size_t)t * D + d];
    float s = v;
#pragma unroll
    for (int o = 16; o; o >>= 1) s += __shfl_xor_sync(0xffffffffu, s, o);
    if ((d & 31) == 0) sred[d >> 5] = s;
    __syncthreads();
    if (d == 0) {
        float m = 0;
#pragma unroll
        for (int i = 0; i < 8; i++) m += sred[i];
        mu_s = m / (float)D;
    }
    __syncthreads();
    const float mu = mu_s;
    const float dv = v - mu;
    float s2 = dv * dv;
#pragma unroll
    for (int o = 16; o; o >>= 1) s2 += __shfl_xor_sync(0xffffffffu, s2, o);
    if ((d & 31) == 0) sred[d >> 5] = s2;
    __syncthreads();
    if (d == 0) {
        float m = 0;
#pragma unroll
        for (int i = 0; i < 8; i++) m += sred[i];
        rs_s = rsqrtf(m / (float)D + 1e-5f);
    }
    __syncthreads();
    row[d] = dv * rs_s * g[d] + be[d];
    __syncthreads();

    if (d < 2 * NOUT) {
        int which = d / NOUT, j = d % NOUT;
        const float* Wm = which ? uw : pw;
        float acc = which ? ub[j] : pb[j];
        for (int dd = 0; dd < D; dd++) acc += row[dd] * Wm[dd * NOUT + j];
        if (which) acc = (acc > 20.0f) ? acc : log1pf(__expf(acc));  // softplus
        out[which * Bn * NOUT + b * NOUT + j] = acc;
    }
}

// ---------------- launch ----------------
extern "C" void kernel_launch(void* const* d_in, const int* in_sizes, int n_in,
                              void* d_out, int out_size) {
    const float* x      = (const float*)d_in[0];
    const float* emb_w  = (const float*)d_in[1];
    const float* emb_b  = (const float*)d_in[2];
    const float* wq     = (const float*)d_in[3];
    const float* wk     = (const float*)d_in[4];
    const float* wv     = (const float*)d_in[5];
    const float* wo     = (const float*)d_in[6];
    const float* wfreq  = (const float*)d_in[7];
    const float* wphase = (const float*)d_in[8];
    const float* rtw    = (const float*)d_in[9];
    const float* rtb    = (const float*)d_in[10];
    const float* ew1    = (const float*)d_in[11];
    const float* eb1    = (const float*)d_in[12];
    const float* ew2    = (const float*)d_in[13];
    const float* eb2    = (const float*)d_in[14];
    const float* ln_g   = (const float*)d_in[15];
    const float* ln_b   = (const float*)d_in[16];
    const float* pred_w = (const float*)d_in[17];
    const float* pred_b = (const float*)d_in[18];
    const float* unc_w  = (const float*)d_in[19];
    const float* unc_b  = (const float*)d_in[20];
    float* out = (float*)d_out;

    float *h, *q, *k, *v, *ao, *hff, *eo;
    cudaGetSymbolAddress((void**)&h,   d_h);
    cudaGetSymbolAddress((void**)&q,   d_qb);
    cudaGetSymbolAddress((void**)&k,   d_kb);
    cudaGetSymbolAddress((void**)&v,   d_vb);
    cudaGetSymbolAddress((void**)&ao,  d_ao);
    cudaGetSymbolAddress((void**)&hff, d_hff);
    cudaGetSymbolAddress((void**)&eo,  d_eo);

    embed_kernel<<<(T * D) / 256, 256>>>(x, emb_w, emb_b, h);

    dim3 gD(T / 128, D / 128);   // (128, 2)
    for (int i = 0; i < NL; i++) {
        sgemm128<<<gD, 256>>>(h, wq + (size_t)i * D * D, nullptr, nullptr, q, D, D, 0);
        sgemm128<<<gD, 256>>>(h, wk + (size_t)i * D * D, nullptr, nullptr, k, D, D, 0);
        sgemm128<<<gD, 256>>>(h, wv + (size_t)i * D * D, nullptr, nullptr, v, D, D, 0);
        attn_kernel<<<Bn * H, 128>>>(q, k, v, wfreq + i * H, wphase + i * H, ao);
        sgemm128<<<gD, 256>>>(ao, wo + (size_t)i * D * D, nullptr, h, h, D, D, 2);

        if (i % 2 == 0) {
            int m = i / 2;
            moe_zero<<<1, 32>>>();
            router_kernel<<<128, 128>>>(h, rtw + (size_t)m * D * NE, rtb + m * NE);
            moe_scan<<<1, 1>>>();
            scatter_kernel<<<(2 * T) / 256, 256>>>();
            moe_gemm128<<<dim3(MAXRB, DFF / 128), 256>>>(
                h, 1, ew1 + (size_t)m * NE * D * DFF, eb1 + (size_t)m * NE * DFF,
                hff, D, DFF, 1);
            moe_gemm128<<<dim3(MAXRB, D / 128), 256>>>(
                hff, 0, ew2 + (size_t)m * NE * DFF * D, eb2 + (size_t)m * NE * D,
                eo, DFF, D, 0);
            combine_kernel<<<(T * D) / 256, 256>>>(h);
        }
    }

    final_kernel<<<Bn, 256>>>(h, ln_g, ln_b, pred_w, pred_b, unc_w, unc_b, out);
}

// round 5
// speedup vs baseline: 1.8343x; 1.5617x over previous
#include <cuda_runtime.h>
#include <math.h>
#include <stdint.h>

// ---------------- problem constants ----------------
namespace {
constexpr int Bn  = 128;
constexpr int Ln  = 128;
constexpr int DIN = 6;
constexpr int D   = 256;
constexpr int H   = 8;
constexpr int NL  = 6;
constexpr int NE  = 8;
constexpr int DFF = 1024;
constexpr int NOUT = 5;
constexpr int T   = Bn * Ln;     // 16384 tokens
constexpr int DK  = 32;
constexpr int MAXRB = 272;       // grouped-GEMM 128-row blocks: 2T/128 + NE pad
constexpr int SSTR = 132;        // padded smem row stride (conflict-free frags)
}

// ---------------- scratch (device globals; no allocation) ----------------
__device__ float d_h [T * D];
__device__ float d_qb[T * D];
__device__ float d_kb[T * D];
__device__ float d_vb[T * D];
__device__ float d_ao[T * D];
__device__ float d_hff[(size_t)2 * T * DFF];   // 134 MB
__device__ float d_eo [(size_t)2 * T * D];     // 33 MB
__device__ int   d_ti  [2 * T];
__device__ float d_tw  [2 * T];
__device__ int   d_posb[2 * T];
__device__ int   d_gtok[2 * T + 512];
__device__ int   d_counts [NE];
__device__ int   d_cursor [NE];
__device__ int   d_offsets[NE];
__device__ int   d_expEnd [NE];
__device__ int   d_blkExpert[MAXRB];
__device__ int   d_blkBase  [MAXRB];
__device__ int   d_numRB;

__device__ __forceinline__ float gelu_exact(float x) {
    return 0.5f * x * (1.0f + erff(x * 0.70710678118654752f));
}

__device__ __forceinline__ uint32_t f2tf32(float x) {
    uint32_t r;
    asm("cvt.rna.tf32.f32 %0, %1;" : "=r"(r) : "f"(x));
    return r;
}

__device__ __forceinline__ void mma_tf32(float c[4], const uint32_t a[4], const uint32_t b[2]) {
    asm volatile(
        "mma.sync.aligned.m16n8k8.row.col.f32.tf32.tf32.f32 "
        "{%0,%1,%2,%3}, {%4,%5,%6,%7}, {%8,%9}, {%0,%1,%2,%3};"
        : "+f"(c[0]), "+f"(c[1]), "+f"(c[2]), "+f"(c[3])
        : "r"(a[0]), "r"(a[1]), "r"(a[2]), "r"(a[3]), "r"(b[0]), "r"(b[1]));
}

// ---------------- embedding: h = x @ emb_w + emb_b ----------------
__global__ void embed_kernel(const float* __restrict__ x,
                             const float* __restrict__ ew,
                             const float* __restrict__ eb,
                             float* __restrict__ h) {
    int idx = blockIdx.x * blockDim.x + threadIdx.x;  // T*D threads
    int t = idx >> 8;
    int d = idx & 255;
    float s = eb[d];
#pragma unroll
    for (int k = 0; k < DIN; k++) s += x[t * DIN + k] * ew[k * D + d];
    h[idx] = s;
}

// ============ 128x128x16 tf32 tensor-core GEMM, 256 threads ============
// C[M,N] = A[M,K] @ W[K,N] (+bias/+resid/gelu). M%128==0, N%128==0, K%16==0.
// flags: bit0=+bias, bit1=+resid, bit2=gelu
// Warps: 4 (m) x 2 (n); warp tile 32x64 = 2 x 8 m16n8k8 fragments.
__global__ void __launch_bounds__(256, 2)
sgemm_tc(const float* __restrict__ A, const float* __restrict__ W,
         const float* __restrict__ bias, const float* __restrict__ resid,
         float* __restrict__ C, int K, int N, int flags) {
    __shared__ uint32_t As[2][16][SSTR];
    __shared__ uint32_t Bs[2][16][SSTR];
    const int bm = blockIdx.x, bn = blockIdx.y;
    const int tid  = threadIdx.x;
    const int wid  = tid >> 5;
    const int lane = tid & 31;
    const int g = lane >> 2, t = lane & 3;
    const int wm = wid & 3, wn = wid >> 2;   // warp grid 4x2

    // loader mapping
    const int arow = tid >> 1;             // 0..127
    const int ak0  = (tid & 1) * 8;        // k base {0,8}
    const int brow = tid >> 5;             // 0..7 (+8 for second)
    const int bcol = (tid & 31) * 4;       // 0..124

    const float* Aptr = A + (size_t)(bm * 128 + arow) * K;
    const float* Wptr = W + (size_t)bn * 128 + bcol;

    float acc[2][8][4] = {};

    // initial tile -> buf 0
    {
        float4 a0 = *(const float4*)(Aptr + ak0);
        float4 a1 = *(const float4*)(Aptr + ak0 + 4);
        As[0][ak0 + 0][arow] = f2tf32(a0.x); As[0][ak0 + 1][arow] = f2tf32(a0.y);
        As[0][ak0 + 2][arow] = f2tf32(a0.z); As[0][ak0 + 3][arow] = f2tf32(a0.w);
        As[0][ak0 + 4][arow] = f2tf32(a1.x); As[0][ak0 + 5][arow] = f2tf32(a1.y);
        As[0][ak0 + 6][arow] = f2tf32(a1.z); As[0][ak0 + 7][arow] = f2tf32(a1.w);
        float4 b0 = *(const float4*)(Wptr + (size_t)brow * N);
        float4 b1 = *(const float4*)(Wptr + (size_t)(brow + 8) * N);
        uint4 u0 = make_uint4(f2tf32(b0.x), f2tf32(b0.y), f2tf32(b0.z), f2tf32(b0.w));
        uint4 u1 = make_uint4(f2tf32(b1.x), f2tf32(b1.y), f2tf32(b1.z), f2tf32(b1.w));
        *(uint4*)&Bs[0][brow][bcol]     = u0;
        *(uint4*)&Bs[0][brow + 8][bcol] = u1;
    }
    __syncthreads();

    const int am0 = wm * 32;     // warp row base in tile
    const int an0 = wn * 64;     // warp col base in tile

    int buf = 0;
    for (int k0 = 0; k0 < K; k0 += 16) {
        const bool more = (k0 + 16) < K;
        float4 pa0, pa1, pb0, pb1;
        if (more) {
            pa0 = *(const float4*)(Aptr + k0 + 16 + ak0);
            pa1 = *(const float4*)(Aptr + k0 + 16 + ak0 + 4);
            pb0 = *(const float4*)(Wptr + (size_t)(k0 + 16 + brow) * N);
            pb1 = *(const float4*)(Wptr + (size_t)(k0 + 16 + brow + 8) * N);
        }
#pragma unroll
        for (int ks = 0; ks < 16; ks += 8) {
            uint32_t af[2][4];
#pragma unroll
            for (int mt = 0; mt < 2; mt++) {
                int m0 = am0 + mt * 16;
                af[mt][0] = As[buf][ks + t][m0 + g];
                af[mt][1] = As[buf][ks + t][m0 + g + 8];
                af[mt][2] = As[buf][ks + t + 4][m0 + g];
                af[mt][3] = As[buf][ks + t + 4][m0 + g + 8];
            }
            uint32_t bf[8][2];
#pragma unroll
            for (int nt = 0; nt < 8; nt++) {
                int n0 = an0 + nt * 8;
                bf[nt][0] = Bs[buf][ks + t][n0 + g];
                bf[nt][1] = Bs[buf][ks + t + 4][n0 + g];
            }
#pragma unroll
            for (int mt = 0; mt < 2; mt++)
#pragma unroll
                for (int nt = 0; nt < 8; nt++)
                    mma_tf32(acc[mt][nt], af[mt], bf[nt]);
        }
        if (more) {
            int nb = buf ^ 1;
            As[nb][ak0 + 0][arow] = f2tf32(pa0.x); As[nb][ak0 + 1][arow] = f2tf32(pa0.y);
            As[nb][ak0 + 2][arow] = f2tf32(pa0.z); As[nb][ak0 + 3][arow] = f2tf32(pa0.w);
            As[nb][ak0 + 4][arow] = f2tf32(pa1.x); As[nb][ak0 + 5][arow] = f2tf32(pa1.y);
            As[nb][ak0 + 6][arow] = f2tf32(pa1.z); As[nb][ak0 + 7][arow] = f2tf32(pa1.w);
            uint4 u0 = make_uint4(f2tf32(pb0.x), f2tf32(pb0.y), f2tf32(pb0.z), f2tf32(pb0.w));
            uint4 u1 = make_uint4(f2tf32(pb1.x), f2tf32(pb1.y), f2tf32(pb1.z), f2tf32(pb1.w));
            *(uint4*)&Bs[nb][brow][bcol]     = u0;
            *(uint4*)&Bs[nb][brow + 8][bcol] = u1;
            __syncthreads();
            buf = nb;
        }
    }

    // epilogue
#pragma unroll
    for (int mt = 0; mt < 2; mt++) {
        int r0 = bm * 128 + am0 + mt * 16 + g;
#pragma unroll
        for (int nt = 0; nt < 8; nt++) {
            int c = bn * 128 + an0 + nt * 8 + t * 2;
            float2 v0 = make_float2(acc[mt][nt][0], acc[mt][nt][1]);  // row r0
            float2 v1 = make_float2(acc[mt][nt][2], acc[mt][nt][3]);  // row r0+8
            if (flags & 1) {
                float b0 = bias[c], b1 = bias[c + 1];
                v0.x += b0; v0.y += b1; v1.x += b0; v1.y += b1;
            }
            if (flags & 2) {
                float2 q0 = *(const float2*)&resid[(size_t)r0 * N + c];
                float2 q1 = *(const float2*)&resid[(size_t)(r0 + 8) * N + c];
                v0.x += q0.x; v0.y += q0.y; v1.x += q1.x; v1.y += q1.y;
            }
            if (flags & 4) {
                v0.x = gelu_exact(v0.x); v0.y = gelu_exact(v0.y);
                v1.x = gelu_exact(v1.x); v1.y = gelu_exact(v1.y);
            }
            *(float2*)&C[(size_t)r0 * N + c]       = v0;
            *(float2*)&C[(size_t)(r0 + 8) * N + c] = v1;
        }
    }
}

// ---------------- wave attention, one block per (b, head) ----------------
__global__ void attn_kernel(const float* __restrict__ Q, const float* __restrict__ K_,
                            const float* __restrict__ V,
                            const float* __restrict__ wf, const float* __restrict__ wp,
                            float* __restrict__ O) {
    const int b = blockIdx.x >> 3;
    const int hh = blockIdx.x & 7;
    __shared__ float ks[Ln][DK];
    __shared__ float vs[Ln][DK];
    __shared__ float wv[Ln];
    const int tid = threadIdx.x;   // 128
    const float freq = wf[hh], phase = wp[hh];
    const float scale = 0.17677669529663687f;  // DK^-0.5

    for (int idx = tid; idx < Ln * DK; idx += 128) {
        int l = idx >> 5, d = idx & 31;
        ks[l][d] = K_[(size_t)(b * Ln + l) * D + hh * DK + d];
        vs[l][d] = V[(size_t)(b * Ln + l) * D + hh * DK + d];
    }
    if (tid < Ln)
        wv[tid] = scale * cosf(6.283185307179586f * freq * (float)tid + phase);
    __syncthreads();

    float qr[DK];
#pragma unroll
    for (int d = 0; d < DK; d++) qr[d] = Q[(size_t)(b * Ln + tid) * D + hh * DK + d];

    float m = -1e30f;
    for (int kk = 0; kk < Ln; kk++) {
        float s = 0.f;
#pragma unroll
        for (int d = 0; d < DK; d++) s += qr[d] * ks[kk][d];
        s *= wv[kk];
        m = fmaxf(m, s);
    }
    float acc[DK] = {};
    float sum = 0.f;
    for (int kk = 0; kk < Ln; kk++) {
        float s = 0.f;
#pragma unroll
        for (int d = 0; d < DK; d++) s += qr[d] * ks[kk][d];
        s *= wv[kk];
        float p = __expf(s - m);
        sum += p;
#pragma unroll
        for (int d = 0; d < DK; d++) acc[d] += p * vs[kk][d];
    }
    const float inv = 1.0f / sum;
#pragma unroll
    for (int d = 0; d < DK; d++)
        O[(size_t)(b * Ln + tid) * D + hh * DK + d] = acc[d] * inv;
}

// ---------------- MoE router ----------------
__global__ void moe_zero() {
    int i = threadIdx.x;
    if (i < NE) { d_counts[i] = 0; }
}

__global__ void router_kernel(const float* __restrict__ h,
                              const float* __restrict__ rtw,
                              const float* __restrict__ rtb) {
    const int gw = (blockIdx.x * blockDim.x + threadIdx.x) >> 5;
    const int lane = threadIdx.x & 31;
    const int nwarp = (gridDim.x * blockDim.x) >> 5;
    for (int t = gw; t < T; t += nwarp) {
        float lg[NE] = {};
        for (int d = lane; d < D; d += 32) {
            float hv = h[(size_t)t * D + d];
#pragma unroll
            for (int e = 0; e < NE; e++) lg[e] += hv * rtw[d * NE + e];
        }
#pragma unroll
        for (int e = 0; e < NE; e++)
#pragma unroll
            for (int off = 16; off; off >>= 1)
                lg[e] += __shfl_xor_sync(0xffffffffu, lg[e], off);
        if (lane == 0) {
#pragma unroll
            for (int e = 0; e < NE; e++) lg[e] += rtb[e];
            int e0 = 0;
#pragma unroll
            for (int e = 1; e < NE; e++) if (lg[e] > lg[e0]) e0 = e;
            int e1 = (e0 == 0) ? 1 : 0;
#pragma unroll
            for (int e = 0; e < NE; e++)
                if (e != e0 && lg[e] > lg[e1]) e1 = e;
            float w0 = 1.0f / (1.0f + __expf(lg[e1] - lg[e0]));
            d_ti[t * 2]     = e0;
            d_ti[t * 2 + 1] = e1;
            d_tw[t * 2]     = w0;
            d_tw[t * 2 + 1] = 1.0f - w0;
            atomicAdd(&d_counts[e0], 1);
            atomicAdd(&d_counts[e1], 1);
        }
    }
}

__global__ void moe_scan() {
    if (threadIdx.x == 0) {
        int off = 0, rb = 0;
        for (int e = 0; e < NE; e++) {
            d_offsets[e] = off;
            int c = d_counts[e];
            d_expEnd[e] = off + c;
            int nb = (c + 127) >> 7;
            for (int j = 0; j < nb; j++) {
                d_blkExpert[rb] = e;
                d_blkBase[rb]   = off + (j << 7);
                rb++;
            }
            off += c;
            d_cursor[e] = 0;
        }
        d_numRB = rb;
    }
}

__global__ void scatter_kernel() {
    int idx = blockIdx.x * blockDim.x + threadIdx.x;
    if (idx >= 2 * T) return;
    int e = d_ti[idx];
    int p = atomicAdd(&d_cursor[e], 1);
    int r = d_offsets[e] + p;
    d_gtok[r]  = idx >> 1;
    d_posb[idx] = r;
}

// ============ grouped expert GEMM, tf32 tensor cores ============
__global__ void __launch_bounds__(256, 2)
moe_gemm_tc(const float* __restrict__ Abase, int useGather,
            const float* __restrict__ Wbase,
            const float* __restrict__ biasBase,
            float* __restrict__ Cbase,
            int K, int N, int actGelu) {
    const int rb = blockIdx.x;
    if (rb >= d_numRB) return;
    const int e    = d_blkExpert[rb];
    const int base = d_blkBase[rb];
    const int rend = d_expEnd[e];
    const float* W    = Wbase + (size_t)e * K * N;
    const float* bias = biasBase + (size_t)e * N;

    __shared__ uint32_t As[2][16][SSTR];
    __shared__ uint32_t Bs[2][16][SSTR];
    const int bn = blockIdx.y;
    const int tid  = threadIdx.x;
    const int wid  = tid >> 5;
    const int lane = tid & 31;
    const int g = lane >> 2, t = lane & 3;
    const int wm = wid & 3, wn = wid >> 2;

    const int arow = tid >> 1;
    const int ak0  = (tid & 1) * 8;
    const int brow = tid >> 5;
    const int bcol = (tid & 31) * 4;

    int r = base + arow;
    bool avalid = r < rend;
    size_t asrc;
    if (useGather) asrc = (size_t)d_gtok[avalid ? r : base];
    else           asrc = (size_t)(avalid ? r : base);
    const float* Aptr = Abase + asrc * K;
    const float* Wptr = W + (size_t)bn * 128 + bcol;

    float acc[2][8][4] = {};

    {
        float4 a0 = *(const float4*)(Aptr + ak0);
        float4 a1 = *(const float4*)(Aptr + ak0 + 4);
        As[0][ak0 + 0][arow] = f2tf32(a0.x); As[0][ak0 + 1][arow] = f2tf32(a0.y);
        As[0][ak0 + 2][arow] = f2tf32(a0.z); As[0][ak0 + 3][arow] = f2tf32(a0.w);
        As[0][ak0 + 4][arow] = f2tf32(a1.x); As[0][ak0 + 5][arow] = f2tf32(a1.y);
        As[0][ak0 + 6][arow] = f2tf32(a1.z); As[0][ak0 + 7][arow] = f2tf32(a1.w);
        float4 b0 = *(const float4*)(Wptr + (size_t)brow * N);
        float4 b1 = *(const float4*)(Wptr + (size_t)(brow + 8) * N);
        uint4 u0 = make_uint4(f2tf32(b0.x), f2tf32(b0.y), f2tf32(b0.z), f2tf32(b0.w));
        uint4 u1 = make_uint4(f2tf32(b1.x), f2tf32(b1.y), f2tf32(b1.z), f2tf32(b1.w));
        *(uint4*)&Bs[0][brow][bcol]     = u0;
        *(uint4*)&Bs[0][brow + 8][bcol] = u1;
    }
    __syncthreads();

    const int am0 = wm * 32;
    const int an0 = wn * 64;

    int buf = 0;
    for (int k0 = 0; k0 < K; k0 += 16) {
        const bool more = (k0 + 16) < K;
        float4 pa0, pa1, pb0, pb1;
        if (more) {
            pa0 = *(const float4*)(Aptr + k0 + 16 + ak0);
            pa1 = *(const float4*)(Aptr + k0 + 16 + ak0 + 4);
            pb0 = *(const float4*)(Wptr + (size_t)(k0 + 16 + brow) * N);
            pb1 = *(const float4*)(Wptr + (size_t)(k0 + 16 + brow + 8) * N);
        }
#pragma unroll
        for (int ks = 0; ks < 16; ks += 8) {
            uint32_t af[2][4];
#pragma unroll
            for (int mt = 0; mt < 2; mt++) {
                int m0 = am0 + mt * 16;
                af[mt][0] = As[buf][ks + t][m0 + g];
                af[mt][1] = As[buf][ks + t][m0 + g + 8];
                af[mt][2] = As[buf][ks + t + 4][m0 + g];
                af[mt][3] = As[buf][ks + t + 4][m0 + g + 8];
            }
            uint32_t bf[8][2];
#pragma unroll
            for (int nt = 0; nt < 8; nt++) {
                int n0 = an0 + nt * 8;
                bf[nt][0] = Bs[buf][ks + t][n0 + g];
                bf[nt][1] = Bs[buf][ks + t + 4][n0 + g];
            }
#pragma unroll
            for (int mt = 0; mt < 2; mt++)
#pragma unroll
                for (int nt = 0; nt < 8; nt++)
                    mma_tf32(acc[mt][nt], af[mt], bf[nt]);
        }
        if (more) {
            int nb = buf ^ 1;
            As[nb][ak0 + 0][arow] = f2tf32(pa0.x); As[nb][ak0 + 1][arow] = f2tf32(pa0.y);
            As[nb][ak0 + 2][arow] = f2tf32(pa0.z); As[nb][ak0 + 3][arow] = f2tf32(pa0.w);
            As[nb][ak0 + 4][arow] = f2tf32(pa1.x); As[nb][ak0 + 5][arow] = f2tf32(pa1.y);
            As[nb][ak0 + 6][arow] = f2tf32(pa1.z); As[nb][ak0 + 7][arow] = f2tf32(pa1.w);
            uint4 u0 = make_uint4(f2tf32(pb0.x), f2tf32(pb0.y), f2tf32(pb0.z), f2tf32(pb0.w));
            uint4 u1 = make_uint4(f2tf32(pb1.x), f2tf32(pb1.y), f2tf32(pb1.z), f2tf32(pb1.w));
            *(uint4*)&Bs[nb][brow][bcol]     = u0;
            *(uint4*)&Bs[nb][brow + 8][bcol] = u1;
            __syncthreads();
            buf = nb;
        }
    }

#pragma unroll
    for (int mt = 0; mt < 2; mt++) {
        int rr0 = base + am0 + mt * 16 + g;   // local segment row
#pragma unroll
        for (int nt = 0; nt < 8; nt++) {
            int c = bn * 128 + an0 + nt * 8 + t * 2;
            float b0 = bias[c], b1 = bias[c + 1];
            if (rr0 < rend) {
                float2 v = make_float2(acc[mt][nt][0] + b0, acc[mt][nt][1] + b1);
                if (actGelu) { v.x = gelu_exact(v.x); v.y = gelu_exact(v.y); }
                *(float2*)&Cbase[(size_t)rr0 * N + c] = v;
            }
            if (rr0 + 8 < rend) {
                float2 v = make_float2(acc[mt][nt][2] + b0, acc[mt][nt][3] + b1);
                if (actGelu) { v.x = gelu_exact(v.x); v.y = gelu_exact(v.y); }
                *(float2*)&Cbase[(size_t)(rr0 + 8) * N + c] = v;
            }
        }
    }
}

// ---------------- combine: h += w0*eo[pos0] + w1*eo[pos1] ----------------
__global__ void combine_kernel(float* __restrict__ h) {
    int idx = blockIdx.x * blockDim.x + threadIdx.x;  // T*D
    int t = idx >> 8;
    int d = idx & 255;
    float a = d_tw[t * 2]     * d_eo[(size_t)d_posb[t * 2]     * D + d];
    float b = d_tw[t * 2 + 1] * d_eo[(size_t)d_posb[t * 2 + 1] * D + d];
    h[idx] += a + b;
}

// ---------------- final LN (last position only) + heads ----------------
__global__ void final_kernel(const float* __restrict__ h,
                             const float* __restrict__ g, const float* __restrict__ be,
                             const float* __restrict__ pw, const float* __restrict__ pb,
                             const float* __restrict__ uw, const float* __restrict__ ub,
                             float* __restrict__ out) {
    const int b = blockIdx.x;
    const int d = threadIdx.x;  // 256
    const int t = b * Ln + (Ln - 1);
    __shared__ float row[D];
    __shared__ float sred[8];
    __shared__ float mu_s, rs_s;

    float v = h[(size_t)t * D + d];
    float s = v;
#pragma unroll
    for (int o = 16; o; o >>= 1) s += __shfl_xor_sync(0xffffffffu, s, o);
    if ((d & 31) == 0) sred[d >> 5] = s;
    __syncthreads();
    if (d == 0) {
        float m = 0;
#pragma unroll
        for (int i = 0; i < 8; i++) m += sred[i];
        mu_s = m / (float)D;
    }
    __syncthreads();
    const float mu = mu_s;
    const float dv = v - mu;
    float s2 = dv * dv;
#pragma unroll
    for (int o = 16; o; o >>= 1) s2 += __shfl_xor_sync(0xffffffffu, s2, o);
    if ((d & 31) == 0) sred[d >> 5] = s2;
    __syncthreads();
    if (d == 0) {
        float m = 0;
#pragma unroll
        for (int i = 0; i < 8; i++) m += sred[i];
        rs_s = rsqrtf(m / (float)D + 1e-5f);
    }
    __syncthreads();
    row[d] = dv * rs_s * g[d] + be[d];
    __syncthreads();

    if (d < 2 * NOUT) {
        int which = d / NOUT, j = d % NOUT;
        const float* Wm = which ? uw : pw;
        float acc = which ? ub[j] : pb[j];
        for (int dd = 0; dd < D; dd++) acc += row[dd] * Wm[dd * NOUT + j];
        if (which) acc = (acc > 20.0f) ? acc : log1pf(__expf(acc));  // softplus
        out[which * Bn * NOUT + b * NOUT + j] = acc;
    }
}

// ---------------- launch ----------------
extern "C" void kernel_launch(void* const* d_in, const int* in_sizes, int n_in,
                              void* d_out, int out_size) {
    const float* x      = (const float*)d_in[0];
    const float* emb_w  = (const float*)d_in[1];
    const float* emb_b  = (const float*)d_in[2];
    const float* wq     = (const float*)d_in[3];
    const float* wk     = (const float*)d_in[4];
    const float* wv     = (const float*)d_in[5];
    const float* wo     = (const float*)d_in[6];
    const float* wfreq  = (const float*)d_in[7];
    const float* wphase = (const float*)d_in[8];
    const float* rtw    = (const float*)d_in[9];
    const float* rtb    = (const float*)d_in[10];
    const float* ew1    = (const float*)d_in[11];
    const float* eb1    = (const float*)d_in[12];
    const float* ew2    = (const float*)d_in[13];
    const float* eb2    = (const float*)d_in[14];
    const float* ln_g   = (const float*)d_in[15];
    const float* ln_b   = (const float*)d_in[16];
    const float* pred_w = (const float*)d_in[17];
    const float* pred_b = (const float*)d_in[18];
    const float* unc_w  = (const float*)d_in[19];
    const float* unc_b  = (const float*)d_in[20];
    float* out = (float*)d_out;

    float *h, *q, *k, *v, *ao, *hff, *eo;
    cudaGetSymbolAddress((void**)&h,   d_h);
    cudaGetSymbolAddress((void**)&q,   d_qb);
    cudaGetSymbolAddress((void**)&k,   d_kb);
    cudaGetSymbolAddress((void**)&v,   d_vb);
    cudaGetSymbolAddress((void**)&ao,  d_ao);
    cudaGetSymbolAddress((void**)&hff, d_hff);
    cudaGetSymbolAddress((void**)&eo,  d_eo);

    embed_kernel<<<(T * D) / 256, 256>>>(x, emb_w, emb_b, h);

    dim3 gD(T / 128, D / 128);   // (128, 2)
    for (int i = 0; i < NL; i++) {
        sgemm_tc<<<gD, 256>>>(h, wq + (size_t)i * D * D, nullptr, nullptr, q, D, D, 0);
        sgemm_tc<<<gD, 256>>>(h, wk + (size_t)i * D * D, nullptr, nullptr, k, D, D, 0);
        sgemm_tc<<<gD, 256>>>(h, wv + (size_t)i * D * D, nullptr, nullptr, v, D, D, 0);
        attn_kernel<<<Bn * H, 128>>>(q, k, v, wfreq + i * H, wphase + i * H, ao);
        sgemm_tc<<<gD, 256>>>(ao, wo + (size_t)i * D * D, nullptr, h, h, D, D, 2);

        if (i % 2 == 0) {
            int m = i / 2;
            moe_zero<<<1, 32>>>();
            router_kernel<<<128, 128>>>(h, rtw + (size_t)m * D * NE, rtb + m * NE);
            moe_scan<<<1, 1>>>();
            scatter_kernel<<<(2 * T) / 256, 256>>>();
            moe_gemm_tc<<<dim3(MAXRB, DFF / 128), 256>>>(
                h, 1, ew1 + (size_t)m * NE * D * DFF, eb1 + (size_t)m * NE * DFF,
                hff, D, DFF, 1);
            moe_gemm_tc<<<dim3(MAXRB, D / 128), 256>>>(
                hff, 0, ew2 + (size_t)m * NE * DFF * D, eb2 + (size_t)m * NE * D,
                eo, DFF, D, 0);
            combine_kernel<<<(T * D) / 256, 256>>>(h);
        }
    }

    final_kernel<<<Bn, 256>>>(h, ln_g, ln_b, pred_w, pred_b, unc_w, unc_b, out);
}